// round 5
// baseline (speedup 1.0000x reference)
#include <cuda_runtime.h>
#include <math.h>

#define EPS 1e-8f
#define THREADS 256

// One CTA per batch row b.
// Phase 1: compute kn[16] (normalized k projection of decoder state) in-block.
// Phase 2: stream the 4096 encoder rows (32 floats each), compute
//          att[s] = (q . kn) / max(||q||, eps) with q = Wq x + bq,
//          x held in registers, Wq via broadcast LDS.128 from smem.
// Phase 3: block-wide log_softmax over S, coalesced store.
__global__ __launch_bounds__(THREADS) void attn_cosine_logsoftmax(
    const float* __restrict__ dec,   // [B,32]
    const float* __restrict__ enc,   // [B,S,32]
    const float* __restrict__ Wq,    // [16,32]
    const float* __restrict__ bq,    // [16]
    const float* __restrict__ Wk,    // [16,32]
    const float* __restrict__ bk,    // [16]
    float* __restrict__ out,         // [B,S] (logical [B,1,S])
    int S)
{
    __shared__ float  s_att[4096];
    __shared__ float4 s_Wq[16 * 8];   // Wq rows, 8 float4 per row
    __shared__ float  s_bq[16];
    __shared__ float  s_kvec[16];
    __shared__ float  s_red[8];
    __shared__ float  s_bcast[2];

    const int b   = blockIdx.x;
    const int tid = threadIdx.x;

    // ---- stage Wq / bq into smem ----
    if (tid < 128) {
        reinterpret_cast<float4*>(s_Wq)[tid] =
            reinterpret_cast<const float4*>(Wq)[tid];
    }
    if (tid < 16) {
        s_bq[tid] = bq[tid];
        // ---- k projection for this batch row (threads 0..15, one d each) ----
        float kd = bk[tid];
        const float* wr = Wk + tid * 32;
        const float* xr = dec + b * 32;
        #pragma unroll
        for (int h = 0; h < 32; h++) kd = fmaf(wr[h], xr[h], kd);
        s_kvec[tid] = kd;
    }
    __syncthreads();

    // every thread builds its private kn[16] (identical values)
    float kn[16];
    {
        float ss = 0.f;
        #pragma unroll
        for (int d = 0; d < 16; d++) { float v = s_kvec[d]; ss = fmaf(v, v, ss); }
        float inv = 1.0f / fmaxf(sqrtf(ss), EPS);
        #pragma unroll
        for (int d = 0; d < 16; d++) kn[d] = s_kvec[d] * inv;
    }

    // ---- main pass over S ----
    const float4* encb = reinterpret_cast<const float4*>(enc) + (size_t)b * S * 8;
    float maxv = -INFINITY;

    #pragma unroll 1
    for (int s = tid; s < S; s += THREADS) {
        const float4* xr = encb + (size_t)s * 8;
        float4 xv[8];
        #pragma unroll
        for (int i = 0; i < 8; i++) xv[i] = xr[i];

        float sumsq = 0.f, dot = 0.f;
        #pragma unroll
        for (int d = 0; d < 16; d++) {
            float qd = s_bq[d];
            #pragma unroll
            for (int i = 0; i < 8; i++) {
                float4 w = s_Wq[d * 8 + i];
                qd = fmaf(w.x, xv[i].x, qd);
                qd = fmaf(w.y, xv[i].y, qd);
                qd = fmaf(w.z, xv[i].z, qd);
                qd = fmaf(w.w, xv[i].w, qd);
            }
            sumsq = fmaf(qd, qd, sumsq);
            dot   = fmaf(qd, kn[d], dot);
        }
        float att = dot / fmaxf(sqrtf(sumsq), EPS);
        s_att[s] = att;
        maxv = fmaxf(maxv, att);
    }

    // ---- block max reduce ----
    #pragma unroll
    for (int o = 16; o; o >>= 1)
        maxv = fmaxf(maxv, __shfl_xor_sync(0xFFFFFFFFu, maxv, o));
    if ((tid & 31) == 0) s_red[tid >> 5] = maxv;
    __syncthreads();   // also publishes s_att writes
    if (tid < 32) {
        float m = (tid < (THREADS / 32)) ? s_red[tid] : -INFINITY;
        #pragma unroll
        for (int o = 4; o; o >>= 1)
            m = fmaxf(m, __shfl_xor_sync(0xFFFFFFFFu, m, o));
        if (tid == 0) s_bcast[0] = m;
    }
    __syncthreads();
    const float gmax = s_bcast[0];

    // ---- sum of exp ----
    float lsum = 0.f;
    #pragma unroll 1
    for (int s = tid; s < S; s += THREADS)
        lsum += __expf(s_att[s] - gmax);

    #pragma unroll
    for (int o = 16; o; o >>= 1)
        lsum += __shfl_xor_sync(0xFFFFFFFFu, lsum, o);
    __syncthreads();   // s_red reuse guard
    if ((tid & 31) == 0) s_red[tid >> 5] = lsum;
    __syncthreads();
    if (tid < 32) {
        float sm = (tid < (THREADS / 32)) ? s_red[tid] : 0.f;
        #pragma unroll
        for (int o = 4; o; o >>= 1)
            sm += __shfl_xor_sync(0xFFFFFFFFu, sm, o);
        if (tid == 0) s_bcast[1] = sm;
    }
    __syncthreads();
    const float lse = gmax + logf(s_bcast[1]);

    // ---- coalesced output ----
    float* ob = out + (size_t)b * S;
    #pragma unroll 1
    for (int s = tid; s < S; s += THREADS)
        ob[s] = s_att[s] - lse;
}

extern "C" void kernel_launch(void* const* d_in, const int* in_sizes, int n_in,
                              void* d_out, int out_size) {
    const float* dec = (const float*)d_in[0];   // [B,32]
    const float* enc = (const float*)d_in[1];   // [B,S,32]
    const float* Wq  = (const float*)d_in[2];   // [16,32]
    const float* bq  = (const float*)d_in[3];   // [16]
    const float* Wk  = (const float*)d_in[4];   // [16,32]
    const float* bk  = (const float*)d_in[5];   // [16]
    float* out = (float*)d_out;

    const int H = 32;
    const int B = in_sizes[0] / H;                 // 512
    const int S = in_sizes[1] / (B * H);           // 4096

    attn_cosine_logsoftmax<<<B, THREADS>>>(dec, enc, Wq, bq, Wk, bk, out, S);
}